// round 3
// baseline (speedup 1.0000x reference)
#include <cuda_runtime.h>
#include <cuda_bf16.h>
#include <math.h>

// Problem constants
#define BB 4
#define DD 768
#define GG 64
#define PP 256
#define HH 12
#define HD 64
#define GP (GG * PP)            // 16384
#define E3D (3 * DD)            // 2304

// Scratch (allocation-free rule: __device__ globals)
__device__ float g_qkv[(size_t)BB * E3D * GP];  // [B, 3D, G, P]
__device__ float g_att[(size_t)BB * DD * GP];   // [B, D, G, P]
__device__ unsigned g_mask[(size_t)GG * PP * 8]; // packed bits: row (g,p), 8 u32
__device__ int g_mask_dtype;                     // 0=u8, 1=i32, 2=f32, 3=bf16

typedef unsigned long long ull;

__device__ __forceinline__ ull pack2(float x, float y) {
    ull r;
    asm("mov.b64 %0, {%1, %2};" : "=l"(r) : "f"(x), "f"(y));
    return r;
}
__device__ __forceinline__ void unpack2(ull v, float& x, float& y) {
    asm("mov.b64 {%0, %1}, %2;" : "=f"(x), "=f"(y) : "l"(v));
}
__device__ __forceinline__ ull fma2(ull a, ull b, ull c) {
    ull d;
    asm("fma.rn.f32x2 %0, %1, %2, %3;" : "=l"(d) : "l"(a), "l"(b), "l"(c));
    return d;
}

// Fast exp2 on FMA pipe (avoids MUFU bottleneck). Degree-6 poly on [-0.5, 0.5].
__device__ __forceinline__ float fexp2(float t) {
    t = fmaxf(t, -120.0f);
    float r = rintf(t);
    float f = t - r;                 // [-0.5, 0.5]
    int   e = (int)r;
    float p = 1.5403530e-4f;
    p = fmaf(p, f, 1.3333558e-3f);
    p = fmaf(p, f, 9.6181291e-3f);
    p = fmaf(p, f, 5.5504109e-2f);
    p = fmaf(p, f, 2.4022651e-1f);
    p = fmaf(p, f, 6.9314718e-1f);
    p = fmaf(p, f, 1.0f);
    return p * __int_as_float((e + 127) << 23);
}

// ---------------------------------------------------------------------------
// Mask dtype detection (deterministic; runs every launch on same data).
// Scans the first 1024 32-bit words of the raw mask buffer.
//   float32 1.0f word = 0x3F800000  -> dtype 2
//   bf16    1.0 pair  = 0x3F803F80  -> dtype 3 (or 0x00003F80 low-half only)
//   uint8   bools: words like 0x01010101 (any value > 1 w/o f32 sig) -> dtype 0
//   int32   bools: words only 0 or 1 -> dtype 1 (default)
// ---------------------------------------------------------------------------
__global__ void detect_mask_dtype(const unsigned* __restrict__ m) {
    if (threadIdx.x != 0 || blockIdx.x != 0) return;
    int dt = 1;  // default: int32
    for (int i = 0; i < 1024; i++) {
        unsigned w = m[i];
        if (w == 0x3F800000u) { dt = 2; break; }                       // float32
        if ((w & 0xFFFFu) == 0x3F80u || (w >> 16) == 0x3F80u) { dt = 3; break; } // bf16
        if (w > 1u) { dt = 0; break; }                                  // uint8
    }
    g_mask_dtype = dt;
}

// One thread per (g,p) query row: pack 256 keep-bits into 8 u32s.
__global__ void pack_mask(const void* __restrict__ mraw) {
    int row = blockIdx.x * blockDim.x + threadIdx.x;  // 0 .. G*P-1
    if (row >= GG * PP) return;
    int dt = g_mask_dtype;
    const size_t base = (size_t)row * PP;
    unsigned bits[8] = {0, 0, 0, 0, 0, 0, 0, 0};
    for (int q = 0; q < PP; q++) {
        bool keep;
        if (dt == 0)      keep = ((const unsigned char*)mraw)[base + q] != 0;
        else if (dt == 1) keep = ((const int*)mraw)[base + q] != 0;
        else if (dt == 2) keep = ((const float*)mraw)[base + q] != 0.0f;
        else              keep = ((const unsigned short*)mraw)[base + q] != 0;
        if (keep) bits[q >> 5] |= 1u << (q & 31);
    }
    unsigned* out = g_mask + (size_t)row * 8;
#pragma unroll
    for (int i = 0; i < 8; i++) out[i] = bits[i];
}

// ---------------------------------------------------------------------------
// SGEMM: C[bz] = A @ B[bz] (+ bias), A: [M,K] row-major (shared over batch),
// B: [K,N] row-major per batch, C: [M,N] per batch.
// 128x128 tile, BK=8, 256 threads, 8x8 per thread via packed f32x2 FMA.
// ---------------------------------------------------------------------------
__global__ __launch_bounds__(256, 2) void sgemm_f32x2(
    const float* __restrict__ A, const float* __restrict__ B,
    float* __restrict__ C, const float* __restrict__ bias,
    int M, int N, int K)
{
    __shared__ float As[2][8][128];
    __shared__ float Bs[2][8][128];

    const int tid = threadIdx.x;
    const int bz = blockIdx.z;
    B += (size_t)bz * K * N;
    C += (size_t)bz * M * N;

    const int row0 = blockIdx.y * 128;
    const int col0 = blockIdx.x * 128;
    const int tx = tid & 15;          // 0..15 -> 8 cols each
    const int ty = tid >> 4;          // 0..15 -> 8 rows each

    const int ar = tid >> 1, ac = (tid & 1) * 4;   // A tile load: 128 rows x 8k
    const int br = tid >> 5, bc = (tid & 31) * 4;  // B tile load: 8k x 128 cols
    const float* Ag = A + (size_t)(row0 + ar) * K + ac;
    const float* Bg = B + (size_t)br * N + col0 + bc;

    ull acc[8][4];
#pragma unroll
    for (int i = 0; i < 8; i++)
#pragma unroll
        for (int j = 0; j < 4; j++) acc[i][j] = 0ull;

    // preload tile 0
    float4 pa = *(const float4*)Ag;
    float4 pb = *(const float4*)Bg;
    As[0][ac + 0][ar] = pa.x; As[0][ac + 1][ar] = pa.y;
    As[0][ac + 2][ar] = pa.z; As[0][ac + 3][ar] = pa.w;
    *(float4*)&Bs[0][br][bc] = pb;
    __syncthreads();

    const int nk = K >> 3;
    int buf = 0;
    for (int kt = 0; kt < nk; kt++) {
        if (kt + 1 < nk) {
            pa = *(const float4*)(Ag + (kt + 1) * 8);
            pb = *(const float4*)(Bg + (size_t)(kt + 1) * 8 * N);
        }
#pragma unroll
        for (int kk = 0; kk < 8; kk++) {
            float4 a0 = *(const float4*)&As[buf][kk][ty * 8];
            float4 a1 = *(const float4*)&As[buf][kk][ty * 8 + 4];
            float4 b0 = *(const float4*)&Bs[buf][kk][tx * 8];
            float4 b1 = *(const float4*)&Bs[buf][kk][tx * 8 + 4];
            ull b2[4];
            b2[0] = pack2(b0.x, b0.y); b2[1] = pack2(b0.z, b0.w);
            b2[2] = pack2(b1.x, b1.y); b2[3] = pack2(b1.z, b1.w);
            float av[8] = {a0.x, a0.y, a0.z, a0.w, a1.x, a1.y, a1.z, a1.w};
#pragma unroll
            for (int i = 0; i < 8; i++) {
                ull a2 = pack2(av[i], av[i]);
#pragma unroll
                for (int j = 0; j < 4; j++) acc[i][j] = fma2(a2, b2[j], acc[i][j]);
            }
        }
        if (kt + 1 < nk) {
            int nb = buf ^ 1;
            As[nb][ac + 0][ar] = pa.x; As[nb][ac + 1][ar] = pa.y;
            As[nb][ac + 2][ar] = pa.z; As[nb][ac + 3][ar] = pa.w;
            *(float4*)&Bs[nb][br][bc] = pb;
            __syncthreads();
            buf = nb;
        }
    }

#pragma unroll
    for (int i = 0; i < 8; i++) {
        int row = row0 + ty * 8 + i;
        float c[8];
#pragma unroll
        for (int j = 0; j < 4; j++) unpack2(acc[i][j], c[2 * j], c[2 * j + 1]);
        if (bias != nullptr) {
            float bv = __ldg(&bias[row]);
#pragma unroll
            for (int j = 0; j < 8; j++) c[j] += bv;
        }
        float4* cp = (float4*)(C + (size_t)row * N + col0 + tx * 8);
        cp[0] = make_float4(c[0], c[1], c[2], c[3]);
        cp[1] = make_float4(c[4], c[5], c[6], c[7]);
    }
}

// ---------------------------------------------------------------------------
// Fused attention: one CTA per (b, h, g). 256 threads = 256 query rows.
// K/V tiles (64x256 fp32 each, [hd][p] layout) in 128 KB dynamic smem.
// q row in registers (pre-scaled by SCALE*log2(e)); online softmax in exp2
// domain using FMA-pipe fexp2. Masked scores -> -1e30 (weight ~2^-120 ~ 0);
// fully-masked rows degenerate to uniform softmax exactly like the reference.
// ---------------------------------------------------------------------------
__global__ __launch_bounds__(256, 1) void attn_kernel(
    const float* __restrict__ qkv, float* __restrict__ outb)
{
    const int g = blockIdx.x, h = blockIdx.y, b = blockIdx.z;
    const int p = threadIdx.x;

    extern __shared__ float sm[];
    float* Ks = sm;              // [64][256]
    float* Vs = sm + 64 * 256;   // [64][256]

    const size_t plane = (size_t)GP;
    const float* gq = qkv + ((size_t)b * E3D + h * HD) * plane + (size_t)g * PP;
    const float* gk = gq + (size_t)DD * plane;
    const float* gv = gq + (size_t)(2 * DD) * plane;

    // cooperative K/V load: coalesced float4 over p, conflict-free smem stores
    for (int idx = threadIdx.x; idx < 64 * 64; idx += 256) {
        int hd = idx >> 6;
        int p4 = (idx & 63) << 2;
        *(float4*)&Ks[hd * 256 + p4] = *(const float4*)&gk[(size_t)hd * plane + p4];
        *(float4*)&Vs[hd * 256 + p4] = *(const float4*)&gv[(size_t)hd * plane + p4];
    }

    // q row into registers, pre-scaled by SCALE * log2(e)
    const float CC = 0.18033688011112042f;  // (1/8) * 1.4426950408889634
    float q[HD];
#pragma unroll
    for (int d = 0; d < HD; d++) q[d] = gq[(size_t)d * plane + p] * CC;

    // this query's packed mask bits: bit q of key q at g_mask[row*8 + q>>5]
    unsigned mbits[8];
    {
        const unsigned* mrow = g_mask + ((size_t)g * PP + p) * 8;
#pragma unroll
        for (int i = 0; i < 8; i++) mbits[i] = mrow[i];
    }

    __syncthreads();

    float m = -INFINITY, l = 0.0f;
    float o[HD];
#pragma unroll
    for (int d = 0; d < HD; d++) o[d] = 0.0f;

    const float4* K4 = (const float4*)Ks;
    const float4* V4 = (const float4*)Vs;

    for (int j4 = 0; j4 < 64; j4++) {
        float s0 = 0.f, s1 = 0.f, s2 = 0.f, s3 = 0.f;
#pragma unroll
        for (int d = 0; d < HD; d++) {
            float4 kv = K4[d * 64 + j4];   // broadcast LDS.128
            s0 = fmaf(q[d], kv.x, s0);
            s1 = fmaf(q[d], kv.y, s1);
            s2 = fmaf(q[d], kv.z, s2);
            s3 = fmaf(q[d], kv.w, s3);
        }
        unsigned kp = (mbits[j4 >> 3] >> ((j4 & 7) << 2)) & 0xFu;
        if (!(kp & 1u)) s0 = -1e30f;
        if (!(kp & 2u)) s1 = -1e30f;
        if (!(kp & 4u)) s2 = -1e30f;
        if (!(kp & 8u)) s3 = -1e30f;

        float mx = fmaxf(fmaxf(s0, s1), fmaxf(s2, s3));
        if (mx > m) {
            float al = fexp2(m - mx);
            l *= al;
#pragma unroll
            for (int d = 0; d < HD; d++) o[d] *= al;
            m = mx;
        }
        float w0 = fexp2(s0 - m);
        float w1 = fexp2(s1 - m);
        float w2 = fexp2(s2 - m);
        float w3 = fexp2(s3 - m);
        l += (w0 + w1) + (w2 + w3);
#pragma unroll
        for (int d = 0; d < HD; d++) {
            float4 vv = V4[d * 64 + j4];   // broadcast LDS.128
            o[d] += (w0 * vv.x + w1 * vv.y) + (w2 * vv.z + w3 * vv.w);
        }
    }

    float inv = 1.0f / l;
    float* go = outb + ((size_t)b * DD + h * HD) * plane + (size_t)g * PP + p;
#pragma unroll
    for (int d = 0; d < HD; d++) go[(size_t)d * plane] = o[d] * inv;
}

// ---------------------------------------------------------------------------
extern "C" void kernel_launch(void* const* d_in, const int* in_sizes, int n_in,
                              void* d_out, int out_size)
{
    const float* x      = (const float*)d_in[0];
    const void*  mask   = d_in[1];
    const float* w_qkv  = (const float*)d_in[2];
    const float* w_proj = (const float*)d_in[3];
    const float* b_proj = (const float*)d_in[4];
    float*       out    = (float*)d_out;

    float* qkvbuf = nullptr;
    float* attbuf = nullptr;
    cudaGetSymbolAddress((void**)&qkvbuf, g_qkv);
    cudaGetSymbolAddress((void**)&attbuf, g_att);

    // 0) Mask dtype detection + bit-packing (dtype-agnostic, deterministic)
    detect_mask_dtype<<<1, 32>>>((const unsigned*)mask);
    pack_mask<<<(GG * PP + 255) / 256, 256>>>(mask);

    // 1) QKV projection: per batch [2304x768] @ [768x16384]
    sgemm_f32x2<<<dim3(GP / 128, E3D / 128, BB), 256>>>(
        w_qkv, x, qkvbuf, nullptr, E3D, GP, DD);

    // 2) Fused masked attention per (b, h, g)
    cudaFuncSetAttribute(attn_kernel,
                         cudaFuncAttributeMaxDynamicSharedMemorySize, 131072);
    attn_kernel<<<dim3(GG, HH, BB), 256, 131072>>>(qkvbuf, attbuf);

    // 3) Output projection + bias: per batch [768x768] @ [768x16384]
    sgemm_f32x2<<<dim3(GP / 128, DD / 128, BB), 256>>>(
        w_proj, attbuf, out, b_proj, DD, GP, DD);
}

// round 5
// speedup vs baseline: 1.7067x; 1.7067x over previous
#include <cuda_runtime.h>
#include <cuda_bf16.h>
#include <math.h>
#include <stdint.h>

// Problem constants
#define BB 4
#define DD 768
#define GG 64
#define PP 256
#define HH 12
#define HD 64
#define GP (GG * PP)            // 16384
#define E3D (3 * DD)            // 2304
#define KK 768                  // K dim of both GEMMs
#define NT GP                   // N total of both GEMMs

// ---------------- scratch (allocation-free rule: __device__ globals) -------
__device__ __align__(256) float g_qkv[(size_t)BB * E3D * GP];          // [B, 3D, G*P]
__device__ __align__(256) __nv_bfloat16 g_xT_hi[(size_t)BB * GP * DD]; // x^T  [B, N, K]
__device__ __align__(256) __nv_bfloat16 g_xT_lo[(size_t)BB * GP * DD];
__device__ __align__(256) __nv_bfloat16 g_aT_hi[(size_t)BB * GP * DD]; // att^T [B, N, K]
__device__ __align__(256) __nv_bfloat16 g_aT_lo[(size_t)BB * GP * DD];
__device__ __align__(256) __nv_bfloat16 g_wq_hi[(size_t)E3D * DD];
__device__ __align__(256) __nv_bfloat16 g_wq_lo[(size_t)E3D * DD];
__device__ __align__(256) __nv_bfloat16 g_wp_hi[(size_t)DD * DD];
__device__ __align__(256) __nv_bfloat16 g_wp_lo[(size_t)DD * DD];
__device__ unsigned g_mask[(size_t)GG * PP * 8];   // packed keep-bits per (g,p)
__device__ int g_mask_dtype;                       // 0=u8,1=i32,2=f32,3=bf16

typedef unsigned long long ull;

// ---------------- small PTX helpers ----------------------------------------
__device__ __forceinline__ ull pack2(float x, float y) {
    ull r; asm("mov.b64 %0, {%1, %2};" : "=l"(r) : "f"(x), "f"(y)); return r;
}
__device__ __forceinline__ void unpack2(ull v, float& x, float& y) {
    asm("mov.b64 {%0, %1}, %2;" : "=f"(x), "=f"(y) : "l"(v));
}
__device__ __forceinline__ ull fma2(ull a, ull b, ull c) {
    ull d; asm("fma.rn.f32x2 %0, %1, %2, %3;" : "=l"(d) : "l"(a), "l"(b), "l"(c));
    return d;
}
__device__ __forceinline__ uint32_t smem_u32(const void* p) {
    uint32_t a;
    asm("{ .reg .u64 t; cvta.to.shared.u64 t, %1; cvt.u32.u64 %0, t; }"
        : "=r"(a) : "l"(p));
    return a;
}
__device__ __forceinline__ void ldsm4(uint32_t& r0, uint32_t& r1, uint32_t& r2,
                                      uint32_t& r3, uint32_t addr) {
    asm volatile("ldmatrix.sync.aligned.m8n8.x4.shared.b16 {%0,%1,%2,%3}, [%4];"
                 : "=r"(r0), "=r"(r1), "=r"(r2), "=r"(r3) : "r"(addr));
}
__device__ __forceinline__ void mma16816(float* c, const uint32_t* a, const uint32_t* b) {
    asm volatile(
        "mma.sync.aligned.m16n8k16.row.col.f32.bf16.bf16.f32 "
        "{%0,%1,%2,%3}, {%4,%5,%6,%7}, {%8,%9}, {%0,%1,%2,%3};"
        : "+f"(c[0]), "+f"(c[1]), "+f"(c[2]), "+f"(c[3])
        : "r"(a[0]), "r"(a[1]), "r"(a[2]), "r"(a[3]), "r"(b[0]), "r"(b[1]));
}

// Fast exp2 on FMA pipe (avoids MUFU bottleneck). Degree-6 poly on [-0.5, 0.5].
__device__ __forceinline__ float fexp2(float t) {
    t = fmaxf(t, -120.0f);
    float r = rintf(t);
    float f = t - r;
    int   e = (int)r;
    float p = 1.5403530e-4f;
    p = fmaf(p, f, 1.3333558e-3f);
    p = fmaf(p, f, 9.6181291e-3f);
    p = fmaf(p, f, 5.5504109e-2f);
    p = fmaf(p, f, 2.4022651e-1f);
    p = fmaf(p, f, 6.9314718e-1f);
    p = fmaf(p, f, 1.0f);
    return p * __int_as_float((e + 127) << 23);
}

// ---------------------------------------------------------------------------
// Mask dtype detection + packing
// ---------------------------------------------------------------------------
__global__ void detect_mask_dtype(const unsigned* __restrict__ m) {
    if (threadIdx.x != 0 || blockIdx.x != 0) return;
    int dt = 1;
    for (int i = 0; i < 1024; i++) {
        unsigned w = m[i];
        if (w == 0x3F800000u) { dt = 2; break; }
        if ((w & 0xFFFFu) == 0x3F80u || (w >> 16) == 0x3F80u) { dt = 3; break; }
        if (w > 1u) { dt = 0; break; }
    }
    g_mask_dtype = dt;
}

__global__ void pack_mask(const void* __restrict__ mraw) {
    int idx = blockIdx.x * blockDim.x + threadIdx.x;
    if (idx >= GG * PP * 8) return;
    int row = idx >> 3, w = idx & 7;
    int dt = g_mask_dtype;
    size_t base = (size_t)row * PP + w * 32;
    unsigned bits = 0;
    for (int t = 0; t < 32; t++) {
        bool keep;
        if (dt == 0)      keep = ((const unsigned char*)mraw)[base + t] != 0;
        else if (dt == 1) keep = ((const int*)mraw)[base + t] != 0;
        else if (dt == 2) keep = ((const float*)mraw)[base + t] != 0.0f;
        else              keep = ((const unsigned short*)mraw)[base + t] != 0;
        if (keep) bits |= 1u << t;
    }
    g_mask[idx] = bits;
}

// ---------------------------------------------------------------------------
// fp32 -> bf16 hi/lo split (weights, elementwise)
// ---------------------------------------------------------------------------
__global__ void conv_split(const float* __restrict__ in, __nv_bfloat16* __restrict__ hi,
                           __nv_bfloat16* __restrict__ lo, int n) {
    for (int i = blockIdx.x * blockDim.x + threadIdx.x; i < n; i += gridDim.x * blockDim.x) {
        float v = in[i];
        __nv_bfloat16 h = __float2bfloat16(v);
        hi[i] = h;
        lo[i] = __float2bfloat16(v - __bfloat162float(h));
    }
}

// x [B, K=768, N=16384] fp32 -> xT hi/lo [B, N, K] bf16 (transposed split)
__global__ void conv_xT(const float* __restrict__ x) {
    __shared__ float t[32][33];
    int bz = blockIdx.z;
    int n0 = blockIdx.x * 32, k0 = blockIdx.y * 32;
    int tx = threadIdx.x, ty = threadIdx.y;
    const float* xp = x + ((size_t)bz * DD + k0) * GP + n0;
    for (int i = ty; i < 32; i += 8) t[i][tx] = xp[(size_t)i * GP + tx];
    __syncthreads();
    for (int r = ty; r < 32; r += 8) {
        float v = t[tx][r];
        size_t o = ((size_t)bz * GP + n0 + r) * DD + k0 + tx;
        __nv_bfloat16 h = __float2bfloat16(v);
        g_xT_hi[o] = h;
        g_xT_lo[o] = __float2bfloat16(v - __bfloat162float(h));
    }
}

// ---------------------------------------------------------------------------
// Warp-MMA GEMM (baseline-ISA tensor cores): C[bz] = A @ B[bz]^T (+ bias)
//   A  : [Mtot, K] bf16 hi/lo (K-major), shared over batch
//   B^T: [NT, K]  bf16 hi/lo (K-major), per batch
//   C  : [Mtot, NT] fp32 per batch
// CTA 128x128, 8 warps (2m x 4n), warp tile 64x32, K-chunk 32, double-buffered
// smem (80B padded rows -> conflict-free ldmatrix). 3 split-products per step:
// Ah*Bh + Ah*Bl + Al*Bh, fp32 accumulate (compensated bf16 ~ 1e-5 rel err).
// ---------------------------------------------------------------------------
__global__ __launch_bounds__(256, 1) void gemm_mma(
    const __nv_bfloat16* __restrict__ Ah, const __nv_bfloat16* __restrict__ Al,
    const __nv_bfloat16* __restrict__ Bh_, const __nv_bfloat16* __restrict__ Bl_,
    float* __restrict__ C, const float* __restrict__ bias, int Mtot)
{
    extern __shared__ char smem[];
    const int tid = threadIdx.x;
    const int wid = tid >> 5, lane = tid & 31;
    const int bz = blockIdx.z;
    const int row0 = blockIdx.y * 128, col0 = blockIdx.x * 128;
    const __nv_bfloat16* Bh = Bh_ + (size_t)bz * NT * KK;
    const __nv_bfloat16* Bl = Bl_ + (size_t)bz * NT * KK;
    float* Cb = C + (size_t)bz * (size_t)Mtot * NT;

    const int warpM = (wid & 1) * 64;
    const int warpN = (wid >> 1) * 32;

    // smem: rows padded to 80B (32 bf16 data + 16B pad) -> bank-spread ldmatrix
    const uint32_t OAH = 0, OAL = 10240, OBH = 20480, OBL = 30720;
    const uint32_t ST = 40960;                     // stage stride (40KB)
    const uint32_t sb = smem_u32(smem);

    // gmem <-> smem indexing: thread owns one row-half (two 16B chunks)
    const int lr = tid >> 1;                       // row 0..127
    const int lc = (tid & 1) * 2;                  // first 16B-chunk index (0 or 2)
    const size_t ga = (size_t)(row0 + lr) * KK + lc * 8;
    const size_t gb = (size_t)(col0 + lr) * KK + lc * 8;
    const uint32_t ss = lr * 80 + lc * 16;         // smem byte offset within tile

    // ldmatrix lane roles
    const int t0 = lane & 7, sel = lane >> 3;
    const uint32_t a_lrow = (warpM + t0 + ((sel & 1) << 3)) * 80 + ((sel >> 1) << 4);
    const uint32_t b_lrow = (warpN + t0 + ((sel >> 1) << 3)) * 80 + ((sel & 1) << 4);

    float acc[4][4][4];
#pragma unroll
    for (int i = 0; i < 4; i++)
#pragma unroll
        for (int j = 0; j < 4; j++)
#pragma unroll
            for (int r = 0; r < 4; r++) acc[i][j][r] = 0.0f;

    uint4 pah[2], pal[2], pbh[2], pbl[2];
    // preload chunk 0
#pragma unroll
    for (int u = 0; u < 2; u++) {
        pah[u] = *(const uint4*)(Ah + ga + u * 8);
        pal[u] = *(const uint4*)(Al + ga + u * 8);
        pbh[u] = *(const uint4*)(Bh + gb + u * 8);
        pbl[u] = *(const uint4*)(Bl + gb + u * 8);
    }
#pragma unroll
    for (int u = 0; u < 2; u++) {
        *(uint4*)(smem + OAH + ss + u * 16) = pah[u];
        *(uint4*)(smem + OAL + ss + u * 16) = pal[u];
        *(uint4*)(smem + OBH + ss + u * 16) = pbh[u];
        *(uint4*)(smem + OBL + ss + u * 16) = pbl[u];
    }
    __syncthreads();

    const int NCH = KK / 32;   // 24
    for (int c = 0; c < NCH; c++) {
        if (c + 1 < NCH) {
            const size_t ko = (size_t)(c + 1) * 32;
#pragma unroll
            for (int u = 0; u < 2; u++) {
                pah[u] = *(const uint4*)(Ah + ga + ko + u * 8);
                pal[u] = *(const uint4*)(Al + ga + ko + u * 8);
                pbh[u] = *(const uint4*)(Bh + gb + ko + u * 8);
                pbl[u] = *(const uint4*)(Bl + gb + ko + u * 8);
            }
        }
        const uint32_t so = sb + (uint32_t)(c & 1) * ST;
#pragma unroll
        for (int ks = 0; ks < 2; ks++) {
            uint32_t ah[4][4], al[4][4], bh[4][2], bl[4][2];
#pragma unroll
            for (int mt = 0; mt < 4; mt++) {
                const uint32_t ad = so + a_lrow + mt * 16 * 80 + ks * 32;
                ldsm4(ah[mt][0], ah[mt][1], ah[mt][2], ah[mt][3], ad + OAH);
                ldsm4(al[mt][0], al[mt][1], al[mt][2], al[mt][3], ad + OAL);
            }
#pragma unroll
            for (int ntp = 0; ntp < 2; ntp++) {
                const uint32_t bd = so + b_lrow + ntp * 16 * 80 + ks * 32;
                ldsm4(bh[2 * ntp][0], bh[2 * ntp][1], bh[2 * ntp + 1][0],
                      bh[2 * ntp + 1][1], bd + OBH);
                ldsm4(bl[2 * ntp][0], bl[2 * ntp][1], bl[2 * ntp + 1][0],
                      bl[2 * ntp + 1][1], bd + OBL);
            }
#pragma unroll
            for (int mt = 0; mt < 4; mt++)
#pragma unroll
                for (int nt = 0; nt < 4; nt++) {
                    mma16816(acc[mt][nt], ah[mt], bh[nt]);
                    mma16816(acc[mt][nt], ah[mt], bl[nt]);
                    mma16816(acc[mt][nt], al[mt], bh[nt]);
                }
        }
        __syncthreads();
        if (c + 1 < NCH) {
            const uint32_t dst = (uint32_t)((c + 1) & 1) * ST + ss;
#pragma unroll
            for (int u = 0; u < 2; u++) {
                *(uint4*)(smem + OAH + dst + u * 16) = pah[u];
                *(uint4*)(smem + OAL + dst + u * 16) = pal[u];
                *(uint4*)(smem + OBH + dst + u * 16) = pbh[u];
                *(uint4*)(smem + OBL + dst + u * 16) = pbl[u];
            }
            __syncthreads();
        }
    }

    // epilogue: fragment -> gmem, bias by M-row
    const int gID = lane >> 2, tig = lane & 3;
#pragma unroll
    for (int mt = 0; mt < 4; mt++) {
#pragma unroll
        for (int half = 0; half < 2; half++) {
            const int row = row0 + warpM + mt * 16 + gID + half * 8;
            const float bv = bias ? __ldg(&bias[row]) : 0.0f;
            float* cp = Cb + (size_t)row * NT + col0 + warpN + tig * 2;
#pragma unroll
            for (int nt = 0; nt < 4; nt++) {
                float2 v = make_float2(acc[mt][nt][half * 2 + 0] + bv,
                                       acc[mt][nt][half * 2 + 1] + bv);
                *(float2*)(cp + nt * 8) = v;
            }
        }
    }
}

// ---------------------------------------------------------------------------
// Fused attention: one CTA per (b, h, g). 256 threads = 256 query rows.
// K/V in 128KB smem ([hd][p] fp32). QK^T via packed f32x2. Online softmax in
// exp2 domain (FMA-pipe fexp2). Output written directly as transposed bf16
// hi/lo split for GEMM2's B operand.
// ---------------------------------------------------------------------------
__global__ __launch_bounds__(256, 1) void attn_kernel(const float* __restrict__ qkv)
{
    const int g = blockIdx.x, h = blockIdx.y, b = blockIdx.z;
    const int p = threadIdx.x;

    extern __shared__ float sm[];
    float* Ks = sm;              // [64][256]
    float* Vs = sm + 64 * 256;   // [64][256]

    const size_t plane = (size_t)GP;
    const float* gq = qkv + ((size_t)b * E3D + h * HD) * plane + (size_t)g * PP;
    const float* gk = gq + (size_t)DD * plane;
    const float* gv = gq + (size_t)(2 * DD) * plane;

    for (int idx = threadIdx.x; idx < 64 * 64; idx += 256) {
        int hd = idx >> 6;
        int p4 = (idx & 63) << 2;
        *(float4*)&Ks[hd * 256 + p4] = *(const float4*)&gk[(size_t)hd * plane + p4];
        *(float4*)&Vs[hd * 256 + p4] = *(const float4*)&gv[(size_t)hd * plane + p4];
    }

    const float CC = 0.18033688011112042f;  // (1/8) * log2(e)
    float q[HD];
#pragma unroll
    for (int d = 0; d < HD; d++) q[d] = gq[(size_t)d * plane + p] * CC;

    unsigned mbits[8];
    {
        const unsigned* mrow = g_mask + ((size_t)g * PP + p) * 8;
#pragma unroll
        for (int i = 0; i < 8; i++) mbits[i] = mrow[i];
    }

    __syncthreads();

    float m = -INFINITY, l = 0.0f;
    float o[HD];
#pragma unroll
    for (int d = 0; d < HD; d++) o[d] = 0.0f;

    const ull* K2 = (const ull*)Ks;
    const float4* V4 = (const float4*)Vs;

    for (int j4 = 0; j4 < 64; j4++) {
        ull s01 = 0ull, s23 = 0ull;
#pragma unroll
        for (int d = 0; d < HD; d++) {
            ull qq = pack2(q[d], q[d]);
            s01 = fma2(qq, K2[d * 128 + j4 * 2 + 0], s01);
            s23 = fma2(qq, K2[d * 128 + j4 * 2 + 1], s23);
        }
        float s0, s1, s2, s3;
        unpack2(s01, s0, s1);
        unpack2(s23, s2, s3);

        unsigned kp = (mbits[j4 >> 3] >> ((j4 & 7) << 2)) & 0xFu;
        if (!(kp & 1u)) s0 = -1e30f;
        if (!(kp & 2u)) s1 = -1e30f;
        if (!(kp & 4u)) s2 = -1e30f;
        if (!(kp & 8u)) s3 = -1e30f;

        float mx = fmaxf(fmaxf(s0, s1), fmaxf(s2, s3));
        if (mx > m) {
            float al = fexp2(m - mx);
            l *= al;
#pragma unroll
            for (int d = 0; d < HD; d++) o[d] *= al;
            m = mx;
        }
        float w0 = fexp2(s0 - m);
        float w1 = fexp2(s1 - m);
        float w2 = fexp2(s2 - m);
        float w3 = fexp2(s3 - m);
        l += (w0 + w1) + (w2 + w3);
#pragma unroll
        for (int d = 0; d < HD; d++) {
            float4 vv = V4[d * 64 + j4];
            o[d] += (w0 * vv.x + w1 * vv.y) + (w2 * vv.z + w3 * vv.w);
        }
    }

    // write transposed bf16 hi/lo split: row n = g*256+p, cols h*64..h*64+63
    const float inv = 1.0f / l;
    const size_t orow = ((size_t)b * GP + (size_t)g * PP + p) * DD + h * HD;
#pragma unroll
    for (int d = 0; d < HD; d += 2) {
        float v0 = o[d] * inv, v1 = o[d + 1] * inv;
        __nv_bfloat16 h0 = __float2bfloat16(v0), h1 = __float2bfloat16(v1);
        __nv_bfloat162 hh; hh.x = h0; hh.y = h1;
        __nv_bfloat162 ll2;
        ll2.x = __float2bfloat16(v0 - __bfloat162float(h0));
        ll2.y = __float2bfloat16(v1 - __bfloat162float(h1));
        *(__nv_bfloat162*)(&g_aT_hi[orow + d]) = hh;
        *(__nv_bfloat162*)(&g_aT_lo[orow + d]) = ll2;
    }
}

// ---------------------------------------------------------------------------
extern "C" void kernel_launch(void* const* d_in, const int* in_sizes, int n_in,
                              void* d_out, int out_size)
{
    const float* x      = (const float*)d_in[0];
    const void*  mask   = d_in[1];
    const float* w_qkv  = (const float*)d_in[2];
    const float* w_proj = (const float*)d_in[3];
    const float* b_proj = (const float*)d_in[4];
    float*       out    = (float*)d_out;

    float *qkvbuf = nullptr;
    __nv_bfloat16 *xth, *xtl, *ath, *atl, *wqh, *wql, *wph, *wpl;
    cudaGetSymbolAddress((void**)&qkvbuf, g_qkv);
    cudaGetSymbolAddress((void**)&xth, g_xT_hi);
    cudaGetSymbolAddress((void**)&xtl, g_xT_lo);
    cudaGetSymbolAddress((void**)&ath, g_aT_hi);
    cudaGetSymbolAddress((void**)&atl, g_aT_lo);
    cudaGetSymbolAddress((void**)&wqh, g_wq_hi);
    cudaGetSymbolAddress((void**)&wql, g_wq_lo);
    cudaGetSymbolAddress((void**)&wph, g_wp_hi);
    cudaGetSymbolAddress((void**)&wpl, g_wp_lo);

    // 0) mask dtype detection + bit packing
    detect_mask_dtype<<<1, 32>>>((const unsigned*)mask);
    pack_mask<<<(GG * PP * 8 + 255) / 256, 256>>>(mask);

    // 1) bf16 hi/lo conversions: weights + transposed x
    conv_split<<<1024, 256>>>(w_qkv, wqh, wql, E3D * DD);
    conv_split<<<1024, 256>>>(w_proj, wph, wpl, DD * DD);
    conv_xT<<<dim3(GP / 32, DD / 32, BB), dim3(32, 8)>>>(x);

    const int GEMM_SMEM = 2 * 40960;  // 80KB
    cudaFuncSetAttribute(gemm_mma, cudaFuncAttributeMaxDynamicSharedMemorySize, GEMM_SMEM);
    cudaFuncSetAttribute(attn_kernel, cudaFuncAttributeMaxDynamicSharedMemorySize, 131072);

    // 2) QKV projection on tensor cores: [2304 x 768] @ [768 x 16384] per batch
    gemm_mma<<<dim3(NT / 128, E3D / 128, BB), 256, GEMM_SMEM>>>(
        wqh, wql, xth, xtl, qkvbuf, nullptr, E3D);

    // 3) fused masked attention per (b, h, g) -> transposed bf16 split output
    attn_kernel<<<dim3(GG, HH, BB), 256, 131072>>>(qkvbuf);

    // 4) output projection + bias on tensor cores
    gemm_mma<<<dim3(NT / 128, DD / 128, BB), 256, GEMM_SMEM>>>(
        wph, wpl, ath, atl, out, b_proj, DD);
}